// round 10
// baseline (speedup 1.0000x reference)
#include <cuda_runtime.h>

// Output: [N+2E, 2E+N] = [5120, 5120] float32, row-major.
//   rows [0, N):        [ M (N x E) | 0 | 0 ]
//   rows [N, N+E):      [ 0 | I_E | -M^T (E x N) ]
//   rows [N+E, N+2E):   [ diag(z) | diag(y) | 0 ]
//
// M is read ONCE: each 32x32 transpose tile emits both the -M^T block and the
// corresponding top-block M copy from shared memory.
// Block roles (heavy / latency-critical first):
//   [0, 2048):     BOT : row N+E+e each; 5 f4 stores + z/y diagonal
//   [2048, 4096):  MID : row N+e, cols [0,4096); 4 f4 stores + identity
//   [4096, 5120):  TOPZ: row r, cols [2048,5120); 3 f4 stores (zeros)
//   [5120, 7168):  TR  : M tile -> top copy + -M^T transpose

#define NN   1024
#define EE   2048
#define SIGW 64
#define CC   (2 * EE + NN)   // 5120
#define C4   (CC / 4)        // 1280
#define DTC  1e-6f

#define BOT_B  2048
#define MID_B  2048
#define TOPZ_B 1024
#define TR_B   2048
#define GRID_B (BOT_B + MID_B + TOPZ_B + TR_B)   // 7168

__global__ void __launch_bounds__(256)
coeff_build_kernel(const float* __restrict__ M,
                   const float* __restrict__ params,
                   const float* __restrict__ sw_params,
                   const int*   __restrict__ kinds,
                   const int*   __restrict__ time_ptr,
                   float*       __restrict__ out)
{
    __shared__ float tile[32][33];

    const int b   = blockIdx.x;
    const int tid = threadIdx.x;
    const float4 zero4 = make_float4(0.f, 0.f, 0.f, 0.f);
    float4* out4 = reinterpret_cast<float4*>(out);

    if (b < BOT_B) {
        // ---- BOT: row N+E+e. Full row zeros + z @ col e, y @ col E+e. ----
        const int e = b;
        const int   tm    = *time_ptr;
        const float p     = __ldg(params + e);
        const int   kk    = __ldg(kinds + e);
        const bool  sw_on = __ldg(sw_params + (size_t)e * SIGW + tm) > 0.0f; // sigmoid>0.5 <=> x>0
        const float ndt   = -DTC / p;
        float z, y;
        switch (kk) {
            case 0:  z = -p;                  y = 1.0f;                 break; // R
            case 1:  z = 0.0f;                y = 1.0f;                 break; // IVS
            case 2:  z = 1.0f;                y = 0.0f;                 break; // VC
            case 3:  z = sw_on ? 0.0f : 1.0f; y = sw_on ? 1.0f : 0.0f;  break; // SW
            case 4:  z = ndt;                 y = 1.0f;                 break; // C
            default: z = 1.0f;                y = ndt;                  break; // L
        }
        const int zf4  = e >> 2;
        const int yf4  = 512 + (e >> 2);
        const int comp = e & 3;
        float4* orow = out4 + (size_t)(NN + EE + e) * C4;
        #pragma unroll
        for (int k = 0; k < 5; k++) {
            const int c4 = tid + k * 256;
            float4 v = zero4;
            if (c4 == zf4) ((float*)&v)[comp] = z;
            if (c4 == yf4) ((float*)&v)[comp] = y;
            orow[c4] = v;
        }
        return;
    }

    if (b < BOT_B + MID_B) {
        // ---- MID: row N+e, cols [0,4096): zeros + 1.0 @ col E+e. ----
        const int e    = b - BOT_B;
        const int idf4 = 512 + (e >> 2);
        const int comp = e & 3;
        float4* orow = out4 + (size_t)(NN + e) * C4;
        #pragma unroll
        for (int k = 0; k < 4; k++) {
            const int c4 = tid + k * 256;
            float4 v = zero4;
            if (c4 == idf4) ((float*)&v)[comp] = 1.0f;
            orow[c4] = v;
        }
        return;
    }

    if (b < BOT_B + MID_B + TOPZ_B) {
        // ---- TOPZ: row r, cols [2048,5120) = f4 [512,1280): zeros. ----
        const int r = b - (BOT_B + MID_B);
        float4* orow = out4 + (size_t)r * C4;
        #pragma unroll
        for (int k = 0; k < 3; k++)
            orow[512 + tid + k * 256] = zero4;
        return;
    }

    // ---- TR: one 32x32 M tile -> top-block copy AND -M^T transpose. ----
    {
        const int t  = b - (BOT_B + MID_B + TOPZ_B);
        const int tn = t & 31;              // 32 tiles along n
        const int te = t >> 5;              // 64 tiles along e
        const int n0 = tn * 32;
        const int e0 = te * 32;
        const int tx = tid & 31;
        const int ty = tid >> 5;            // 0..7

        #pragma unroll
        for (int i = 0; i < 4; i++) {
            const int r = ty + i * 8;       // local n
            tile[r][tx] = M[(size_t)(n0 + r) * EE + (e0 + tx)];
        }
        __syncthreads();

        const int r = tid >> 3;             // 0..31
        const int q = tid & 7;              // 0..7 (float4 slot)

        // (a) -M^T: out[N+e0+r][2E+n0+4q .. +3] = -M[n0+4q+j][e0+r]
        {
            float4 v;
            v.x = -tile[q * 4 + 0][r];
            v.y = -tile[q * 4 + 1][r];
            v.z = -tile[q * 4 + 2][r];
            v.w = -tile[q * 4 + 3][r];
            *reinterpret_cast<float4*>(
                out + (size_t)(NN + e0 + r) * CC + (2 * EE + n0 + q * 4)) = v;
        }

        // (b) Top copy: out[n0+r][e0+4q .. +3] = M[n0+r][e0+4q+j]
        {
            float4 u;
            u.x = tile[r][q * 4 + 0];
            u.y = tile[r][q * 4 + 1];
            u.z = tile[r][q * 4 + 2];
            u.w = tile[r][q * 4 + 3];
            *reinterpret_cast<float4*>(
                out + (size_t)(n0 + r) * CC + (e0 + q * 4)) = u;
        }
    }
}

extern "C" void kernel_launch(void* const* d_in, const int* in_sizes, int n_in,
                              void* d_out, int out_size)
{
    const float* M         = (const float*)d_in[0];
    const float* params    = (const float*)d_in[1];
    const float* sw_params = (const float*)d_in[2];
    const int*   kinds     = (const int*)d_in[3];
    const int*   time_ptr  = (const int*)d_in[4];

    coeff_build_kernel<<<GRID_B, 256>>>(M, params, sw_params, kinds, time_ptr,
                                        (float*)d_out);
}